// round 2
// baseline (speedup 1.0000x reference)
#include <cuda_runtime.h>
#include <math.h>

#define S_LEN 2048
#define D_DIM 2048
#define H_NUM 16
#define HD    128
#define B_NUM 2
#define M_ROWS (B_NUM * S_LEN)   // 4096

// Scratch (device globals: no allocation allowed)
__device__ float g_q[(size_t)B_NUM * H_NUM * S_LEN * HD];
__device__ float g_k[(size_t)B_NUM * H_NUM * S_LEN * HD];
__device__ float g_v[(size_t)B_NUM * H_NUM * S_LEN * HD];
__device__ float g_att[(size_t)M_ROWS * D_DIM];

// ---------------------------------------------------------------------------
// SGEMM: C = A(MxK) @ B(KxN), 128x128 tile, KT=8, 256 threads, 8x8 microtile.
// qkv_mode=1: C written in [B,H,S,HD] layout (n0 block spans exactly one head).
// blockIdx.z selects (B,C) pair for the batched QKV projection.
// ---------------------------------------------------------------------------
__global__ __launch_bounds__(256, 2)
void sgemm_kernel(const float* __restrict__ A,
                  const float* __restrict__ B0, const float* __restrict__ B1,
                  const float* __restrict__ B2,
                  float* __restrict__ C0, float* __restrict__ C1,
                  float* __restrict__ C2,
                  int M, int N, int K, int qkv_mode)
{
    int z = blockIdx.z;
    const float* Bm = (z == 0) ? B0 : (z == 1 ? B1 : B2);
    float*       Cz = (z == 0) ? C0 : (z == 1 ? C1 : C2);

    __shared__ __align__(16) float As[2][8][128];  // [k][m] transposed
    __shared__ __align__(16) float Bs[2][8][128];  // [k][n]

    int tid = threadIdx.x;
    int tx = tid & 15, ty = tid >> 4;
    int tx4 = tx * 4, ty4 = ty * 4;
    int m0 = blockIdx.y * 128, n0 = blockIdx.x * 128;

    int arow = tid >> 1;          // 0..127
    int acol = (tid & 1) * 4;     // 0 or 4
    int brow = tid >> 5;          // 0..7
    int bcol = (tid & 31) * 4;    // 0..124

    const float* Ag = A + (size_t)(m0 + arow) * K + acol;
    const float* Bg = Bm + (size_t)brow * N + (n0 + bcol);

    float4 av = *(const float4*)Ag;
    float4 bv = *(const float4*)Bg;
    As[0][acol + 0][arow] = av.x;
    As[0][acol + 1][arow] = av.y;
    As[0][acol + 2][arow] = av.z;
    As[0][acol + 3][arow] = av.w;
    *(float4*)&Bs[0][brow][bcol] = bv;
    __syncthreads();

    float acc[8][8];
#pragma unroll
    for (int i = 0; i < 8; i++)
#pragma unroll
        for (int j = 0; j < 8; j++) acc[i][j] = 0.f;

    int nk = K >> 3;
    for (int t = 0; t < nk; t++) {
        int cur = t & 1, nxt = cur ^ 1;
        if (t + 1 < nk) {
            av = *(const float4*)(Ag + (t + 1) * 8);
            bv = *(const float4*)(Bg + (size_t)(t + 1) * 8 * N);
        }
#pragma unroll
        for (int k = 0; k < 8; k++) {
            float4 a0 = *(const float4*)&As[cur][k][ty4];
            float4 a1 = *(const float4*)&As[cur][k][ty4 + 64];
            float4 b0 = *(const float4*)&Bs[cur][k][tx4];
            float4 b1 = *(const float4*)&Bs[cur][k][tx4 + 64];
            float a[8] = {a0.x, a0.y, a0.z, a0.w, a1.x, a1.y, a1.z, a1.w};
            float b[8] = {b0.x, b0.y, b0.z, b0.w, b1.x, b1.y, b1.z, b1.w};
#pragma unroll
            for (int i = 0; i < 8; i++)
#pragma unroll
                for (int j = 0; j < 8; j++)
                    acc[i][j] = fmaf(a[i], b[j], acc[i][j]);
        }
        if (t + 1 < nk) {
            As[nxt][acol + 0][arow] = av.x;
            As[nxt][acol + 1][arow] = av.y;
            As[nxt][acol + 2][arow] = av.z;
            As[nxt][acol + 3][arow] = av.w;
            *(float4*)&Bs[nxt][brow][bcol] = bv;
        }
        __syncthreads();
    }

#pragma unroll
    for (int ih = 0; ih < 2; ih++) {
#pragma unroll
        for (int i2 = 0; i2 < 4; i2++) {
            int i = ih * 4 + i2;
            int r = m0 + ty4 + ih * 64 + i2;
#pragma unroll
            for (int jh = 0; jh < 2; jh++) {
                int c = n0 + tx4 + jh * 64;
                float4 v = make_float4(acc[i][jh * 4 + 0], acc[i][jh * 4 + 1],
                                       acc[i][jh * 4 + 2], acc[i][jh * 4 + 3]);
                if (!qkv_mode) {
                    *(float4*)&Cz[(size_t)r * N + c] = v;
                } else {
                    int b  = r >> 11;      // r / S_LEN
                    int s  = r & 2047;
                    int h  = c >> 7;       // constant within CTA
                    int hd = c & 127;
                    *(float4*)&Cz[(((size_t)(b * H_NUM + h)) * S_LEN + s) * HD + hd] = v;
                }
            }
        }
    }
}

// ---------------------------------------------------------------------------
// RoPE in-place on Q,K in [BH][S][HD]. Matches reference fp32 pipeline:
// inv_freq in fp32 (exp), angle = fp32(s * f), accurate sincosf.
// angle index j uses inv_freq[j % 64]; rotate_half interleaved pairs.
// ---------------------------------------------------------------------------
__global__ void rope_kernel(float* __restrict__ Qb, float* __restrict__ Kb)
{
    float* X = (blockIdx.y == 0) ? Qb : Kb;
    int flat = blockIdx.x * blockDim.x + threadIdx.x;  // < BH*S*64 = 4194304
    int i  = flat & 63;
    int s  = (flat >> 6) & 2047;
    int bh = flat >> 17;
    size_t base = ((size_t)bh * S_LEN + s) * HD + 2 * i;
    float x0 = X[base], x1 = X[base + 1];
    int j0 = 2 * i, j1 = 2 * i + 1;
    const float nlog = -9.210340372f;  // -ln(10000)
    float f0 = __expf(nlog * (float)(j0 & 63) * (1.0f / 64.0f));
    float f1 = __expf(nlog * (float)(j1 & 63) * (1.0f / 64.0f));
    float a0 = (float)s * f0;
    float a1 = (float)s * f1;
    float c0, s0, c1, s1;
    sincosf(a0, &s0, &c0);
    sincosf(a1, &s1, &c1);
    X[base]     = x0 * c0 - x1 * s0;   // even: x*cos - x_odd*sin
    X[base + 1] = x1 * c1 + x0 * s1;   // odd:  x*cos + x_even*sin
}

// ---------------------------------------------------------------------------
// Flash attention, fp32, causal. One CTA = one (bh, qblock of 64 rows).
// smem: Qst[128][68] (transposed, pre-scaled), Kst[128][68], Vs[64][132],
// Pst[64][68]. 256 threads: 16x16, 4x4 score microtile, 4x8 O microtile.
// ---------------------------------------------------------------------------
#define FA_SMEM_FLOATS (128 * 68 * 2 + 64 * 132 + 64 * 68)
#define FA_SMEM_BYTES  (FA_SMEM_FLOATS * 4)

__global__ __launch_bounds__(256, 1)
void flash_kernel(const float* __restrict__ Q, const float* __restrict__ K,
                  const float* __restrict__ V, float* __restrict__ Out)
{
    extern __shared__ __align__(16) float sm[];
    float* Qst = sm;                  // [128][68]  (hd, m)
    float* Kst = Qst + 128 * 68;      // [128][68]  (hd, n)
    float* Vs  = Kst + 128 * 68;      // [64][132]  (kv, hd)
    float* Pst = Vs + 64 * 132;       // [64][68]   (kv, m)

    int qb = blockIdx.x;
    int bh = blockIdx.y;
    int tid = threadIdx.x;
    int tx = tid & 15, ty = tid >> 4;
    int tx4 = tx * 4, ty4 = ty * 4, tx8 = tx * 8;

    const float scale = 0.08838834764831845f;  // 1/sqrt(128)

    const float* Qg = Q + ((size_t)bh * S_LEN + qb * 64) * HD;
    const float* Kg = K + (size_t)bh * S_LEN * HD;
    const float* Vg = V + (size_t)bh * S_LEN * HD;

    {   // load Q tile transposed + pre-scaled
        int r  = tid >> 2;
        int c0 = (tid & 3) * 32;
#pragma unroll
        for (int u = 0; u < 8; u++) {
            int c = c0 + u * 4;
            float4 v = *(const float4*)(Qg + (size_t)r * HD + c);
            Qst[(c + 0) * 68 + r] = v.x * scale;
            Qst[(c + 1) * 68 + r] = v.y * scale;
            Qst[(c + 2) * 68 + r] = v.z * scale;
            Qst[(c + 3) * 68 + r] = v.w * scale;
        }
    }

    float m_i[4], l_i[4], o[4][8];
#pragma unroll
    for (int i = 0; i < 4; i++) { m_i[i] = -INFINITY; l_i[i] = 0.f; }
#pragma unroll
    for (int i = 0; i < 4; i++)
#pragma unroll
        for (int j = 0; j < 8; j++) o[i][j] = 0.f;

    for (int kb = 0; kb <= qb; kb++) {
        {   // load K (transposed) + V (natural) tiles
            int r  = tid >> 2;
            int c0 = (tid & 3) * 32;
            const float* kg = Kg + ((size_t)(kb * 64 + r)) * HD;
            const float* vg = Vg + ((size_t)(kb * 64 + r)) * HD;
#pragma unroll
            for (int u = 0; u < 8; u++) {
                int c = c0 + u * 4;
                float4 kv = *(const float4*)(kg + c);
                Kst[(c + 0) * 68 + r] = kv.x;
                Kst[(c + 1) * 68 + r] = kv.y;
                Kst[(c + 2) * 68 + r] = kv.z;
                Kst[(c + 3) * 68 + r] = kv.w;
                *(float4*)&Vs[r * 132 + c] = *(const float4*)(vg + c);
            }
        }
        __syncthreads();  // KV ready (and Q on first iter)

        float acc[4][4];
#pragma unroll
        for (int i = 0; i < 4; i++)
#pragma unroll
            for (int j = 0; j < 4; j++) acc[i][j] = 0.f;

#pragma unroll 4
        for (int k = 0; k < 128; k++) {
            float4 a = *(const float4*)&Qst[k * 68 + ty4];
            float4 b = *(const float4*)&Kst[k * 68 + tx4];
            float av[4] = {a.x, a.y, a.z, a.w};
            float bv[4] = {b.x, b.y, b.z, b.w};
#pragma unroll
            for (int i = 0; i < 4; i++)
#pragma unroll
                for (int j = 0; j < 4; j++)
                    acc[i][j] = fmaf(av[i], bv[j], acc[i][j]);
        }

        if (kb == qb) {  // causal mask on diagonal block
#pragma unroll
            for (int i = 0; i < 4; i++)
#pragma unroll
                for (int j = 0; j < 4; j++)
                    if (tx4 + j > ty4 + i) acc[i][j] = -INFINITY;
        }

        // online softmax (rows replicated across the 16 tx lanes)
#pragma unroll
        for (int i = 0; i < 4; i++) {
            float rm = fmaxf(fmaxf(acc[i][0], acc[i][1]), fmaxf(acc[i][2], acc[i][3]));
#pragma unroll
            for (int off = 8; off > 0; off >>= 1)
                rm = fmaxf(rm, __shfl_xor_sync(0xffffffffu, rm, off, 16));
            float m_new = fmaxf(m_i[i], rm);
            float alpha = __expf(m_i[i] - m_new);
            float rs = 0.f;
#pragma unroll
            for (int j = 0; j < 4; j++) {
                acc[i][j] = __expf(acc[i][j] - m_new);
                rs += acc[i][j];
            }
#pragma unroll
            for (int off = 8; off > 0; off >>= 1)
                rs += __shfl_xor_sync(0xffffffffu, rs, off, 16);
            l_i[i] = l_i[i] * alpha + rs;
            m_i[i] = m_new;
#pragma unroll
            for (int j = 0; j < 8; j++) o[i][j] *= alpha;
        }

        // store P transposed [kv][m]
#pragma unroll
        for (int i = 0; i < 4; i++)
#pragma unroll
            for (int j = 0; j < 4; j++)
                Pst[(tx4 + j) * 68 + ty4 + i] = acc[i][j];
        __syncthreads();  // P ready for all threads

        // O += P @ V : rows ty4..+3, cols tx8..+7
#pragma unroll 4
        for (int k = 0; k < 64; k++) {
            float4 p4 = *(const float4*)&Pst[k * 68 + ty4];
            float4 v0 = *(const float4*)&Vs[k * 132 + tx8];
            float4 v1 = *(const float4*)&Vs[k * 132 + tx8 + 4];
            float pv[4] = {p4.x, p4.y, p4.z, p4.w};
            float vv[8] = {v0.x, v0.y, v0.z, v0.w, v1.x, v1.y, v1.z, v1.w};
#pragma unroll
            for (int i = 0; i < 4; i++)
#pragma unroll
                for (int j = 0; j < 8; j++)
                    o[i][j] = fmaf(pv[i], vv[j], o[i][j]);
        }
        __syncthreads();  // protect Kst/Vs/Pst before next iteration
    }

    // epilogue: normalize, write [B][S][D]
    int b = bh >> 4;
    int h = bh & 15;
#pragma unroll
    for (int i = 0; i < 4; i++) {
        float inv = 1.0f / l_i[i];
        size_t row = (size_t)b * S_LEN + qb * 64 + ty4 + i;
        float* dst = Out + row * D_DIM + h * HD + tx8;
        *(float4*)dst = make_float4(o[i][0] * inv, o[i][1] * inv,
                                    o[i][2] * inv, o[i][3] * inv);
        *(float4*)(dst + 4) = make_float4(o[i][4] * inv, o[i][5] * inv,
                                          o[i][6] * inv, o[i][7] * inv);
    }
}

// ---------------------------------------------------------------------------
extern "C" void kernel_launch(void* const* d_in, const int* in_sizes, int n_in,
                              void* d_out, int out_size)
{
    const float* x  = (const float*)d_in[0];
    const float* Wq = (const float*)d_in[1];
    const float* Wk = (const float*)d_in[2];
    const float* Wv = (const float*)d_in[3];
    const float* Wo = (const float*)d_in[4];
    float* out = (float*)d_out;

    float *pq, *pk, *pv, *pa;
    cudaGetSymbolAddress((void**)&pq, g_q);
    cudaGetSymbolAddress((void**)&pk, g_k);
    cudaGetSymbolAddress((void**)&pv, g_v);
    cudaGetSymbolAddress((void**)&pa, g_att);

    cudaFuncSetAttribute(flash_kernel,
                         cudaFuncAttributeMaxDynamicSharedMemorySize,
                         FA_SMEM_BYTES);

    // 1) Q,K,V projections (batched over z), written to [B,H,S,HD]
    dim3 gqkv(D_DIM / 128, M_ROWS / 128, 3);
    sgemm_kernel<<<gqkv, 256>>>(x, Wq, Wk, Wv, pq, pk, pv,
                                M_ROWS, D_DIM, D_DIM, 1);

    // 2) RoPE in-place on Q and K
    rope_kernel<<<dim3(4194304 / 256, 2), 256>>>(pq, pk);

    // 3) causal flash attention -> g_att in [B,S,D]
    flash_kernel<<<dim3(S_LEN / 64, B_NUM * H_NUM), 256, FA_SMEM_BYTES>>>(
        pq, pk, pv, pa);

    // 4) output projection -> d_out
    dim3 gout(D_DIM / 128, M_ROWS / 128, 1);
    sgemm_kernel<<<gout, 256>>>(pa, Wo, Wo, Wo, out, out, out,
                                M_ROWS, D_DIM, D_DIM, 0);
}

// round 4
// speedup vs baseline: 1.5978x; 1.5978x over previous
#include <cuda_runtime.h>
#include <cuda_bf16.h>
#include <math.h>
#include <stdint.h>

#define S_LEN 2048
#define D_DIM 2048
#define H_NUM 16
#define HD    128
#define B_NUM 2
#define M_ROWS (B_NUM * S_LEN)   // 4096
#define KDIM  2048

// ---------------------------------------------------------------------------
// Scratch (device globals: no allocation allowed)
// ---------------------------------------------------------------------------
__device__ float g_q[(size_t)B_NUM * H_NUM * S_LEN * HD];
__device__ float g_k[(size_t)B_NUM * H_NUM * S_LEN * HD];
__device__ float g_v[(size_t)B_NUM * H_NUM * S_LEN * HD];
__device__ float g_att[(size_t)M_ROWS * D_DIM];
__device__ __nv_bfloat16 g_ah[(size_t)M_ROWS * KDIM];          // A hi split
__device__ __nv_bfloat16 g_al[(size_t)M_ROWS * KDIM];          // A lo split
__device__ __nv_bfloat16 g_wth[(size_t)4 * D_DIM * KDIM];      // W^T hi (Wq,Wk,Wv,Wo)
__device__ __nv_bfloat16 g_wtl[(size_t)4 * D_DIM * KDIM];      // W^T lo

// ---------------------------------------------------------------------------
// Helpers (all legal on plain sm_103: cp.async sm_80+, ldmatrix sm_75+,
// mma.sync bf16 sm_80+; NO tcgen05 / 'a'-gated features anywhere)
// ---------------------------------------------------------------------------
__device__ __forceinline__ uint32_t smem_u32(const void* p) {
    uint32_t a;
    asm("{ .reg .u64 t; cvta.to.shared.u64 t, %1; cvt.u32.u64 %0, t; }"
        : "=r"(a) : "l"(p));
    return a;
}

__device__ __forceinline__ void cp16(uint32_t sm_dst, const void* g_src) {
    asm volatile("cp.async.cg.shared.global [%0], [%1], 16;"
                 :: "r"(sm_dst), "l"(g_src));
}
#define CP_COMMIT() asm volatile("cp.async.commit_group;" ::: "memory")
#define CP_WAIT1()  asm volatile("cp.async.wait_group 1;" ::: "memory")
#define CP_WAIT0()  asm volatile("cp.async.wait_group 0;" ::: "memory")

__device__ __forceinline__ void ldsm4(uint32_t* r, uint32_t addr) {
    asm volatile("ldmatrix.sync.aligned.m8n8.x4.shared.b16 {%0,%1,%2,%3}, [%4];"
                 : "=r"(r[0]), "=r"(r[1]), "=r"(r[2]), "=r"(r[3]) : "r"(addr));
}

__device__ __forceinline__ void mma_bf16(float* d, const uint32_t* a,
                                         const uint32_t* b) {
    asm volatile(
        "mma.sync.aligned.m16n8k16.row.col.f32.bf16.bf16.f32 "
        "{%0,%1,%2,%3}, {%4,%5,%6,%7}, {%8,%9}, {%0,%1,%2,%3};"
        : "+f"(d[0]), "+f"(d[1]), "+f"(d[2]), "+f"(d[3])
        : "r"(a[0]), "r"(a[1]), "r"(a[2]), "r"(a[3]), "r"(b[0]), "r"(b[1]));
}

// ---------------------------------------------------------------------------
// bf16-split GEMM via mma.sync: C[M,N] = A[M,K] * W[K,N], W pre-transposed
// K-major (WT[n][k]). 3-term split: Ah*Bh + Ah*Bl + Al*Bh, fp32 accumulate.
// CTA tile 128x128, BK=32, 8 warps (warp tile 32x64), 3-stage cp.async ring.
// smem row stride 80B (pad 64->80): ldmatrix 8-row phases are conflict-free.
// qkv_mode=1: output written in [B,H,S,HD] layout.
// ---------------------------------------------------------------------------
#define MG_BK 32
#define MG_NC (KDIM / MG_BK)        // 64
#define MAT_BYTES (128 * 80)        // 10240 per matrix (128 rows x 80B)
#define STAGE_B (4 * MAT_BYTES)     // Ah, Al, Bh, Bl = 40960
#define MG_SMEM (3 * STAGE_B)       // 122880

__device__ __forceinline__ void mg_load(
    uint32_t st, const __nv_bfloat16* Ah, const __nv_bfloat16* Al,
    const __nv_bfloat16* Bh, const __nv_bfloat16* Bl,
    int m0, int n0, int k0, int tid)
{
    int lrow = tid >> 2;           // 0..63
    int lch  = tid & 3;            // 16B chunk (8 bf16)
#pragma unroll
    for (int i = 0; i < 2; i++) {
        int r = lrow + 64 * i;
        uint32_t off = (uint32_t)r * 80 + lch * 16;
        size_t ga = (size_t)(m0 + r) * KDIM + k0 + lch * 8;
        size_t gb = (size_t)(n0 + r) * KDIM + k0 + lch * 8;
        cp16(st + off,                 Ah + ga);
        cp16(st + MAT_BYTES + off,     Al + ga);
        cp16(st + 2 * MAT_BYTES + off, Bh + gb);
        cp16(st + 3 * MAT_BYTES + off, Bl + gb);
    }
}

__global__ __launch_bounds__(256)
void mma_gemm_kernel(const __nv_bfloat16* __restrict__ Ah,
                     const __nv_bfloat16* __restrict__ Al,
                     const __nv_bfloat16* __restrict__ WtH,
                     const __nv_bfloat16* __restrict__ WtL,
                     float* C0, float* C1, float* C2,
                     int wbase, int qkv_mode)
{
    extern __shared__ __align__(256) char smem[];
    uint32_t sb = smem_u32(smem);
    int tid = threadIdx.x;
    int wid = tid >> 5, lane = tid & 31;
    int z = blockIdx.z;

    const __nv_bfloat16* Bh = WtH + (size_t)(wbase + z) * D_DIM * KDIM;
    const __nv_bfloat16* Bl = WtL + (size_t)(wbase + z) * D_DIM * KDIM;
    float* C = (z == 0) ? C0 : (z == 1 ? C1 : C2);
    int m0 = blockIdx.y * 128;
    int n0 = blockIdx.x * 128;

    int wm = wid & 3;              // 4 warps along M (32 rows each)
    int wn = wid >> 2;             // 2 warps along N (64 cols each)

    float acc[2][8][4];
#pragma unroll
    for (int i = 0; i < 2; i++)
#pragma unroll
        for (int j = 0; j < 8; j++)
#pragma unroll
            for (int t = 0; t < 4; t++) acc[i][j][t] = 0.f;

    // prologue: preload chunks 0,1 into stages 0,1
    mg_load(sb,           Ah, Al, Bh, Bl, m0, n0, 0,     tid); CP_COMMIT();
    mg_load(sb + STAGE_B, Ah, Al, Bh, Bl, m0, n0, MG_BK, tid); CP_COMMIT();

    // precomputed ldmatrix lane addressing
    int a_row  = wm * 32 + (lane & 15);
    uint32_t a_koff = ((lane >> 4) & 1) * 16;          // bytes
    int b_row  = wn * 64 + (lane & 7) + (((lane >> 4) & 1) << 3);
    uint32_t b_koff = ((lane >> 3) & 1) * 16;          // bytes

    for (int c = 0; c < MG_NC; c++) {
        if (c + 2 >= MG_NC) { CP_WAIT0(); } else { CP_WAIT1(); }
        __syncthreads();
        uint32_t u = sb + (uint32_t)(c % 3) * STAGE_B;
        uint32_t uAh = u, uAl = u + MAT_BYTES;
        uint32_t uBh = u + 2 * MAT_BYTES, uBl = u + 3 * MAT_BYTES;

#pragma unroll
        for (int ks = 0; ks < 2; ks++) {
            uint32_t kb = ks * 32;   // 16 bf16 = 32B
            uint32_t ah[2][4], al[2][4], bh[4][4], bl[4][4];
            uint32_t ao = (uint32_t)a_row * 80 + a_koff + kb;
            ldsm4(ah[0], uAh + ao);
            ldsm4(ah[1], uAh + ao + 16 * 80);
            ldsm4(al[0], uAl + ao);
            ldsm4(al[1], uAl + ao + 16 * 80);
#pragma unroll
            for (int j = 0; j < 4; j++) {
                uint32_t bo = (uint32_t)(b_row + j * 16) * 80 + b_koff + kb;
                ldsm4(bh[j], uBh + bo);
                ldsm4(bl[j], uBl + bo);
            }
#pragma unroll
            for (int i = 0; i < 2; i++)
#pragma unroll
                for (int j = 0; j < 4; j++) {
                    mma_bf16(acc[i][2 * j],     ah[i], &bh[j][0]);
                    mma_bf16(acc[i][2 * j + 1], ah[i], &bh[j][2]);
                    mma_bf16(acc[i][2 * j],     ah[i], &bl[j][0]);
                    mma_bf16(acc[i][2 * j + 1], ah[i], &bl[j][2]);
                    mma_bf16(acc[i][2 * j],     al[i], &bh[j][0]);
                    mma_bf16(acc[i][2 * j + 1], al[i], &bh[j][2]);
                }
        }

        if (c + 2 < MG_NC) {
            mg_load(sb + (uint32_t)((c + 2) % 3) * STAGE_B,
                    Ah, Al, Bh, Bl, m0, n0, (c + 2) * MG_BK, tid);
            CP_COMMIT();
        }
    }

    // epilogue
    int r0 = m0 + wm * 32 + (lane >> 2);
    int c0 = n0 + wn * 64 + (lane & 3) * 2;
#pragma unroll
    for (int i = 0; i < 2; i++) {
#pragma unroll
        for (int j = 0; j < 8; j++) {
            int gn = c0 + j * 8;
#pragma unroll
            for (int half = 0; half < 2; half++) {
                int gm = r0 + i * 16 + half * 8;
                float2 v = make_float2(acc[i][j][2 * half],
                                       acc[i][j][2 * half + 1]);
                if (!qkv_mode) {
                    *(float2*)&C[(size_t)gm * D_DIM + gn] = v;
                } else {
                    int b = gm >> 11, s = gm & 2047;
                    int h = gn >> 7, hd = gn & 127;
                    *(float2*)&C[(((size_t)(b * H_NUM + h) * S_LEN) + s) * HD + hd] = v;
                }
            }
        }
    }
}

// ---------------------------------------------------------------------------
// fp32 -> (hi, lo) bf16 split, 4 elems/thread
// ---------------------------------------------------------------------------
__global__ void split_kernel(const float* __restrict__ X,
                             __nv_bfloat16* __restrict__ Hh,
                             __nv_bfloat16* __restrict__ Ll)
{
    size_t i = ((size_t)blockIdx.x * blockDim.x + threadIdx.x) * 4;
    float4 v = *(const float4*)(X + i);
    __nv_bfloat16 h0 = __float2bfloat16(v.x);
    __nv_bfloat16 h1 = __float2bfloat16(v.y);
    __nv_bfloat16 h2 = __float2bfloat16(v.z);
    __nv_bfloat16 h3 = __float2bfloat16(v.w);
    __nv_bfloat16 l0 = __float2bfloat16(v.x - __bfloat162float(h0));
    __nv_bfloat16 l1 = __float2bfloat16(v.y - __bfloat162float(h1));
    __nv_bfloat16 l2 = __float2bfloat16(v.z - __bfloat162float(h2));
    __nv_bfloat16 l3 = __float2bfloat16(v.w - __bfloat162float(h3));
    __nv_bfloat162* hp = (__nv_bfloat162*)(Hh + i);
    __nv_bfloat162* lp = (__nv_bfloat162*)(Ll + i);
    hp[0] = __nv_bfloat162(h0, h1); hp[1] = __nv_bfloat162(h2, h3);
    lp[0] = __nv_bfloat162(l0, l1); lp[1] = __nv_bfloat162(l2, l3);
}

// ---------------------------------------------------------------------------
// Weight transpose + split: W[K,N] fp32 -> Wt_hi/Wt_lo [N,K] bf16, z = 0..3
// ---------------------------------------------------------------------------
__global__ void wtrans_kernel(const float* __restrict__ W0, const float* __restrict__ W1,
                              const float* __restrict__ W2, const float* __restrict__ W3,
                              __nv_bfloat16* __restrict__ TH,
                              __nv_bfloat16* __restrict__ TL)
{
    __shared__ float t[32][33];
    int z = blockIdx.z;
    const float* W = (z == 0) ? W0 : (z == 1 ? W1 : (z == 2 ? W2 : W3));
    __nv_bfloat16* th = TH + (size_t)z * D_DIM * KDIM;
    __nv_bfloat16* tl = TL + (size_t)z * D_DIM * KDIM;
    int k0 = blockIdx.y * 32, n0 = blockIdx.x * 32;
    int tx = threadIdx.x, ty = threadIdx.y;   // (32, 8)
#pragma unroll
    for (int i = 0; i < 4; i++)
        t[ty + 8 * i][tx] = W[(size_t)(k0 + ty + 8 * i) * D_DIM + n0 + tx];
    __syncthreads();
#pragma unroll
    for (int i = 0; i < 4; i++) {
        float v = t[tx][ty + 8 * i];
        __nv_bfloat16 h = __float2bfloat16(v);
        __nv_bfloat16 l = __float2bfloat16(v - __bfloat162float(h));
        size_t o = (size_t)(n0 + ty + 8 * i) * KDIM + k0 + tx;
        th[o] = h;
        tl[o] = l;
    }
}

// ---------------------------------------------------------------------------
// RoPE in-place on Q,K in [BH][S][HD]. EXACT Round-2 version (which passed):
// angle[j] = s * theta^{-(j&63)/64}; even/odd lanes use DIFFERENT angles.
// ---------------------------------------------------------------------------
__global__ void rope_kernel(float* __restrict__ Qb, float* __restrict__ Kb)
{
    float* X = (blockIdx.y == 0) ? Qb : Kb;
    int flat = blockIdx.x * blockDim.x + threadIdx.x;  // < BH*S*64 = 4194304
    int i  = flat & 63;
    int s  = (flat >> 6) & 2047;
    int bh = flat >> 17;
    size_t base = ((size_t)bh * S_LEN + s) * HD + 2 * i;
    float x0 = X[base], x1 = X[base + 1];
    int j0 = 2 * i, j1 = 2 * i + 1;
    const float nlog = -9.210340372f;  // -ln(10000)
    float f0 = __expf(nlog * (float)(j0 & 63) * (1.0f / 64.0f));
    float f1 = __expf(nlog * (float)(j1 & 63) * (1.0f / 64.0f));
    float a0 = (float)s * f0;
    float a1 = (float)s * f1;
    float c0, s0, c1, s1;
    sincosf(a0, &s0, &c0);
    sincosf(a1, &s1, &c1);
    X[base]     = x0 * c0 - x1 * s0;   // even: x*cos - x_odd*sin
    X[base + 1] = x1 * c1 + x0 * s1;   // odd:  x*cos + x_even*sin
}

// ---------------------------------------------------------------------------
// Flash attention, fp32, causal (unchanged from the passing Round-2 kernel).
// ---------------------------------------------------------------------------
#define FA_SMEM_FLOATS (128 * 68 * 2 + 64 * 132 + 64 * 68)
#define FA_SMEM_BYTES  (FA_SMEM_FLOATS * 4)

__global__ __launch_bounds__(256, 1)
void flash_kernel(const float* __restrict__ Q, const float* __restrict__ K,
                  const float* __restrict__ V, float* __restrict__ Out)
{
    extern __shared__ __align__(16) float sm[];
    float* Qst = sm;                  // [128][68]
    float* Kst = Qst + 128 * 68;      // [128][68]
    float* Vs  = Kst + 128 * 68;      // [64][132]
    float* Pst = Vs + 64 * 132;       // [64][68]

    int qb = blockIdx.x;
    int bh = blockIdx.y;
    int tid = threadIdx.x;
    int tx = tid & 15, ty = tid >> 4;
    int tx4 = tx * 4, ty4 = ty * 4, tx8 = tx * 8;

    const float scale = 0.08838834764831845f;  // 1/sqrt(128)

    const float* Qg = Q + ((size_t)bh * S_LEN + qb * 64) * HD;
    const float* Kg = K + (size_t)bh * S_LEN * HD;
    const float* Vg = V + (size_t)bh * S_LEN * HD;

    {
        int r  = tid >> 2;
        int c0 = (tid & 3) * 32;
#pragma unroll
        for (int u = 0; u < 8; u++) {
            int c = c0 + u * 4;
            float4 v = *(const float4*)(Qg + (size_t)r * HD + c);
            Qst[(c + 0) * 68 + r] = v.x * scale;
            Qst[(c + 1) * 68 + r] = v.y * scale;
            Qst[(c + 2) * 68 + r] = v.z * scale;
            Qst[(c + 3) * 68 + r] = v.w * scale;
        }
    }

    float m_i[4], l_i[4], o[4][8];
#pragma unroll
    for (int i = 0; i < 4; i++) { m_i[i] = -INFINITY; l_i[i] = 0.f; }
#pragma unroll
    for (int i = 0; i < 4; i++)
#pragma unroll
        for (int j = 0; j < 8; j++) o[i][j] = 0.f;

    for (int kb = 0; kb <= qb; kb++) {
        {
            int r  = tid >> 2;
            int c0 = (tid & 3) * 32;
            const float* kg = Kg + ((size_t)(kb * 64 + r)) * HD;
            const float* vg = Vg + ((size_t)(kb * 64 + r)) * HD;
#pragma unroll
            for (int u = 0; u < 8; u++) {
                int c = c0 + u * 4;
                float4 kv = *(const float4*)(kg + c);
                Kst[(c + 0) * 68 + r] = kv.x;
                Kst[(c + 1) * 68 + r] = kv.y;
                Kst[(c + 2) * 68 + r] = kv.z;
                Kst[(c + 3) * 68 + r] = kv.w;
                *(float4*)&Vs[r * 132 + c] = *(const float4*)(vg + c);
            }
        }
        __syncthreads();

        float acc[4][4];
#pragma unroll
        for (int i = 0; i < 4; i++)
#pragma unroll
            for (int j = 0; j < 4; j++) acc[i][j] = 0.f;

#pragma unroll 4
        for (int k = 0; k < 128; k++) {
            float4 a = *(const float4*)&Qst[k * 68 + ty4];
            float4 b = *(const float4*)&Kst[k * 68 + tx4];
            float av[4] = {a.x, a.y, a.z, a.w};
            float bv[4] = {b.x, b.y, b.z, b.w};
#pragma unroll
            for (int i = 0; i < 4; i++)
#pragma unroll
                for (int j = 0; j < 4; j++)
                    acc[i][j] = fmaf(av[i], bv[j], acc[i][j]);
        }

        if (kb == qb) {
#pragma unroll
            for (int i = 0; i < 4; i++)
#pragma unroll
                for (int j = 0; j < 4; j++)
                    if (tx4 + j > ty4 + i) acc[i][j] = -INFINITY;
        }

#pragma unroll
        for (int i = 0; i < 4; i++) {
            float rm = fmaxf(fmaxf(acc[i][0], acc[i][1]), fmaxf(acc[i][2], acc[i][3]));
#pragma unroll
            for (int off = 8; off > 0; off >>= 1)
                rm = fmaxf(rm, __shfl_xor_sync(0xffffffffu, rm, off, 16));
            float m_new = fmaxf(m_i[i], rm);
            float alpha = __expf(m_i[i] - m_new);
            float rs = 0.f;
#pragma unroll
            for (int j = 0; j < 4; j++) {
                acc[i][j] = __expf(acc[i][j] - m_new);
                rs += acc[i][j];
            }
#pragma unroll
            for (int off = 8; off > 0; off >>= 1)
                rs += __shfl_xor_sync(0xffffffffu, rs, off, 16);
            l_i[i] = l_i[i] * alpha + rs;
            m_i[i] = m_new;
#pragma unroll
            for (int j = 0; j < 8; j++) o[i][j] *= alpha;
        }

#pragma unroll
        for (int i = 0; i < 4; i++)
#pragma unroll
            for (int j = 0; j < 4; j++)
                Pst[(tx4 + j) * 68 + ty4 + i] = acc[i][j];
        __syncthreads();

#pragma unroll 4
        for (int k = 0; k < 64; k++) {
            float4 p4 = *(const float4*)&Pst[k * 68 + ty4];
            float4 v0 = *(const float4*)&Vs[k * 132 + tx8];
            float4 v1 = *(const float4*)&Vs[k * 132 + tx8 + 4];
            float pv[4] = {p4.x, p4.y, p4.z, p4.w};
            float vv[8] = {v0.x, v0.y, v0.z, v0.w, v1.x, v1.y, v1.z, v1.w};
#pragma unroll
            for (int i = 0; i < 4; i++)
#pragma unroll
                for (int j = 0; j < 8; j++)
                    o[i][j] = fmaf(pv[i], vv[j], o[i][j]);
        }
        __syncthreads();
    }

    int b = bh >> 4;
    int h = bh & 15;
#pragma unroll
    for (int i = 0; i < 4; i++) {
        float inv = 1.0f / l_i[i];
        size_t row = (size_t)b * S_LEN + qb * 64 + ty4 + i;
        float* dst = Out + row * D_DIM + h * HD + tx8;
        *(float4*)dst = make_float4(o[i][0] * inv, o[i][1] * inv,
                                    o[i][2] * inv, o[i][3] * inv);
        *(float4*)(dst + 4) = make_float4(o[i][4] * inv, o[i][5] * inv,
                                          o[i][6] * inv, o[i][7] * inv);
    }
}

// ---------------------------------------------------------------------------
extern "C" void kernel_launch(void* const* d_in, const int* in_sizes, int n_in,
                              void* d_out, int out_size)
{
    const float* x  = (const float*)d_in[0];
    const float* Wq = (const float*)d_in[1];
    const float* Wk = (const float*)d_in[2];
    const float* Wv = (const float*)d_in[3];
    const float* Wo = (const float*)d_in[4];
    float* out = (float*)d_out;

    float *pq, *pk, *pv, *pa;
    __nv_bfloat16 *pah, *pal, *pwh, *pwl;
    cudaGetSymbolAddress((void**)&pq,  g_q);
    cudaGetSymbolAddress((void**)&pk,  g_k);
    cudaGetSymbolAddress((void**)&pv,  g_v);
    cudaGetSymbolAddress((void**)&pa,  g_att);
    cudaGetSymbolAddress((void**)&pah, g_ah);
    cudaGetSymbolAddress((void**)&pal, g_al);
    cudaGetSymbolAddress((void**)&pwh, g_wth);
    cudaGetSymbolAddress((void**)&pwl, g_wtl);

    cudaFuncSetAttribute(mma_gemm_kernel,
                         cudaFuncAttributeMaxDynamicSharedMemorySize, MG_SMEM);
    cudaFuncSetAttribute(flash_kernel,
                         cudaFuncAttributeMaxDynamicSharedMemorySize, FA_SMEM_BYTES);

    // 1) bf16 splits of x and the (transposed) weights
    split_kernel<<<(M_ROWS * KDIM / 4) / 256, 256>>>(x, pah, pal);
    wtrans_kernel<<<dim3(D_DIM / 32, KDIM / 32, 4), dim3(32, 8)>>>(
        Wq, Wk, Wv, Wo, pwh, pwl);

    // 2) QKV projections (tensor cores via mma.sync), write [B,H,S,HD]
    mma_gemm_kernel<<<dim3(D_DIM / 128, M_ROWS / 128, 3), 256, MG_SMEM>>>(
        pah, pal, pwh, pwl, pq, pk, pv, 0, 1);

    // 3) RoPE in-place on Q and K
    rope_kernel<<<dim3(4194304 / 256, 2), 256>>>(pq, pk);

    // 4) causal flash attention -> g_att in [B,S,D]
    flash_kernel<<<dim3(S_LEN / 64, B_NUM * H_NUM), 256, FA_SMEM_BYTES>>>(
        pq, pk, pv, pa);

    // 5) split attention output, then O projection -> d_out
    split_kernel<<<(M_ROWS * KDIM / 4) / 256, 256>>>(pa, pah, pal);
    mma_gemm_kernel<<<dim3(D_DIM / 128, M_ROWS / 128, 1), 256, MG_SMEM>>>(
        pah, pal, pwh, pwl, out, out, out, 3, 0);
}

// round 5
// speedup vs baseline: 2.9049x; 1.8180x over previous
#include <cuda_runtime.h>
#include <cuda_bf16.h>
#include <math.h>
#include <stdint.h>

#define S_LEN 2048
#define D_DIM 2048
#define H_NUM 16
#define HD    128
#define B_NUM 2
#define M_ROWS (B_NUM * S_LEN)   // 4096
#define KDIM  2048
#define BH_NUM (B_NUM * H_NUM)   // 32

// ---------------------------------------------------------------------------
// Scratch (device globals: no allocation allowed)
// ---------------------------------------------------------------------------
__device__ float g_q[(size_t)BH_NUM * S_LEN * HD];
__device__ float g_k[(size_t)BH_NUM * S_LEN * HD];
__device__ float g_v[(size_t)BH_NUM * S_LEN * HD];
__device__ float g_att[(size_t)M_ROWS * D_DIM];
__device__ __nv_bfloat16 g_ah[(size_t)M_ROWS * KDIM];
__device__ __nv_bfloat16 g_al[(size_t)M_ROWS * KDIM];
__device__ __nv_bfloat16 g_wth[(size_t)4 * D_DIM * KDIM];
__device__ __nv_bfloat16 g_wtl[(size_t)4 * D_DIM * KDIM];
__device__ __nv_bfloat16 g_qh[(size_t)BH_NUM * S_LEN * HD];
__device__ __nv_bfloat16 g_ql[(size_t)BH_NUM * S_LEN * HD];
__device__ __nv_bfloat16 g_kh[(size_t)BH_NUM * S_LEN * HD];
__device__ __nv_bfloat16 g_kl[(size_t)BH_NUM * S_LEN * HD];
__device__ __nv_bfloat16 g_vh[(size_t)BH_NUM * S_LEN * HD];
__device__ __nv_bfloat16 g_vl[(size_t)BH_NUM * S_LEN * HD];

// ---------------------------------------------------------------------------
// Helpers (plain sm_103-legal: cp.async, ldmatrix, mma.sync bf16)
// ---------------------------------------------------------------------------
__device__ __forceinline__ uint32_t smem_u32(const void* p) {
    uint32_t a;
    asm("{ .reg .u64 t; cvta.to.shared.u64 t, %1; cvt.u32.u64 %0, t; }"
        : "=r"(a) : "l"(p));
    return a;
}

__device__ __forceinline__ void cp16(uint32_t sm_dst, const void* g_src) {
    asm volatile("cp.async.cg.shared.global [%0], [%1], 16;"
                 :: "r"(sm_dst), "l"(g_src));
}
#define CP_COMMIT() asm volatile("cp.async.commit_group;" ::: "memory")
#define CP_WAIT1()  asm volatile("cp.async.wait_group 1;" ::: "memory")
#define CP_WAIT0()  asm volatile("cp.async.wait_group 0;" ::: "memory")

__device__ __forceinline__ void ldsm4(uint32_t* r, uint32_t addr) {
    asm volatile("ldmatrix.sync.aligned.m8n8.x4.shared.b16 {%0,%1,%2,%3}, [%4];"
                 : "=r"(r[0]), "=r"(r[1]), "=r"(r[2]), "=r"(r[3]) : "r"(addr));
}
__device__ __forceinline__ void ldsm4t(uint32_t* r, uint32_t addr) {
    asm volatile("ldmatrix.sync.aligned.m8n8.x4.trans.shared.b16 {%0,%1,%2,%3}, [%4];"
                 : "=r"(r[0]), "=r"(r[1]), "=r"(r[2]), "=r"(r[3]) : "r"(addr));
}

__device__ __forceinline__ void mma_bf16(float* d, const uint32_t* a,
                                         const uint32_t* b) {
    asm volatile(
        "mma.sync.aligned.m16n8k16.row.col.f32.bf16.bf16.f32 "
        "{%0,%1,%2,%3}, {%4,%5,%6,%7}, {%8,%9}, {%0,%1,%2,%3};"
        : "+f"(d[0]), "+f"(d[1]), "+f"(d[2]), "+f"(d[3])
        : "r"(a[0]), "r"(a[1]), "r"(a[2]), "r"(a[3]), "r"(b[0]), "r"(b[1]));
}

// ---------------------------------------------------------------------------
// bf16-split GEMM via mma.sync (unchanged from Round 4, PASSED)
// ---------------------------------------------------------------------------
#define MG_BK 32
#define MG_NC (KDIM / MG_BK)        // 64
#define MAT_BYTES (128 * 80)
#define STAGE_B (4 * MAT_BYTES)
#define MG_SMEM (3 * STAGE_B)       // 122880

__device__ __forceinline__ void mg_load(
    uint32_t st, const __nv_bfloat16* Ah, const __nv_bfloat16* Al,
    const __nv_bfloat16* Bh, const __nv_bfloat16* Bl,
    int m0, int n0, int k0, int tid)
{
    int lrow = tid >> 2;
    int lch  = tid & 3;
#pragma unroll
    for (int i = 0; i < 2; i++) {
        int r = lrow + 64 * i;
        uint32_t off = (uint32_t)r * 80 + lch * 16;
        size_t ga = (size_t)(m0 + r) * KDIM + k0 + lch * 8;
        size_t gb = (size_t)(n0 + r) * KDIM + k0 + lch * 8;
        cp16(st + off,                 Ah + ga);
        cp16(st + MAT_BYTES + off,     Al + ga);
        cp16(st + 2 * MAT_BYTES + off, Bh + gb);
        cp16(st + 3 * MAT_BYTES + off, Bl + gb);
    }
}

__global__ __launch_bounds__(256)
void mma_gemm_kernel(const __nv_bfloat16* __restrict__ Ah,
                     const __nv_bfloat16* __restrict__ Al,
                     const __nv_bfloat16* __restrict__ WtH,
                     const __nv_bfloat16* __restrict__ WtL,
                     float* C0, float* C1, float* C2,
                     int wbase, int qkv_mode)
{
    extern __shared__ __align__(256) char smem[];
    uint32_t sb = smem_u32(smem);
    int tid = threadIdx.x;
    int wid = tid >> 5, lane = tid & 31;
    int z = blockIdx.z;

    const __nv_bfloat16* Bh = WtH + (size_t)(wbase + z) * D_DIM * KDIM;
    const __nv_bfloat16* Bl = WtL + (size_t)(wbase + z) * D_DIM * KDIM;
    float* C = (z == 0) ? C0 : (z == 1 ? C1 : C2);
    int m0 = blockIdx.y * 128;
    int n0 = blockIdx.x * 128;

    int wm = wid & 3;
    int wn = wid >> 2;

    float acc[2][8][4];
#pragma unroll
    for (int i = 0; i < 2; i++)
#pragma unroll
        for (int j = 0; j < 8; j++)
#pragma unroll
            for (int t = 0; t < 4; t++) acc[i][j][t] = 0.f;

    mg_load(sb,           Ah, Al, Bh, Bl, m0, n0, 0,     tid); CP_COMMIT();
    mg_load(sb + STAGE_B, Ah, Al, Bh, Bl, m0, n0, MG_BK, tid); CP_COMMIT();

    int a_row  = wm * 32 + (lane & 15);
    uint32_t a_koff = ((lane >> 4) & 1) * 16;
    int b_row  = wn * 64 + (lane & 7) + (((lane >> 4) & 1) << 3);
    uint32_t b_koff = ((lane >> 3) & 1) * 16;

    for (int c = 0; c < MG_NC; c++) {
        if (c + 2 >= MG_NC) { CP_WAIT0(); } else { CP_WAIT1(); }
        __syncthreads();
        uint32_t u = sb + (uint32_t)(c % 3) * STAGE_B;
        uint32_t uAh = u, uAl = u + MAT_BYTES;
        uint32_t uBh = u + 2 * MAT_BYTES, uBl = u + 3 * MAT_BYTES;

#pragma unroll
        for (int ks = 0; ks < 2; ks++) {
            uint32_t kb = ks * 32;
            uint32_t ah[2][4], al[2][4], bh[4][4], bl[4][4];
            uint32_t ao = (uint32_t)a_row * 80 + a_koff + kb;
            ldsm4(ah[0], uAh + ao);
            ldsm4(ah[1], uAh + ao + 16 * 80);
            ldsm4(al[0], uAl + ao);
            ldsm4(al[1], uAl + ao + 16 * 80);
#pragma unroll
            for (int j = 0; j < 4; j++) {
                uint32_t bo = (uint32_t)(b_row + j * 16) * 80 + b_koff + kb;
                ldsm4(bh[j], uBh + bo);
                ldsm4(bl[j], uBl + bo);
            }
#pragma unroll
            for (int i = 0; i < 2; i++)
#pragma unroll
                for (int j = 0; j < 4; j++) {
                    mma_bf16(acc[i][2 * j],     ah[i], &bh[j][0]);
                    mma_bf16(acc[i][2 * j + 1], ah[i], &bh[j][2]);
                    mma_bf16(acc[i][2 * j],     ah[i], &bl[j][0]);
                    mma_bf16(acc[i][2 * j + 1], ah[i], &bl[j][2]);
                    mma_bf16(acc[i][2 * j],     al[i], &bh[j][0]);
                    mma_bf16(acc[i][2 * j + 1], al[i], &bh[j][2]);
                }
        }

        if (c + 2 < MG_NC) {
            mg_load(sb + (uint32_t)((c + 2) % 3) * STAGE_B,
                    Ah, Al, Bh, Bl, m0, n0, (c + 2) * MG_BK, tid);
            CP_COMMIT();
        }
    }

    int r0 = m0 + wm * 32 + (lane >> 2);
    int c0 = n0 + wn * 64 + (lane & 3) * 2;
#pragma unroll
    for (int i = 0; i < 2; i++) {
#pragma unroll
        for (int j = 0; j < 8; j++) {
            int gn = c0 + j * 8;
#pragma unroll
            for (int half = 0; half < 2; half++) {
                int gm = r0 + i * 16 + half * 8;
                float2 v = make_float2(acc[i][j][2 * half],
                                       acc[i][j][2 * half + 1]);
                if (!qkv_mode) {
                    *(float2*)&C[(size_t)gm * D_DIM + gn] = v;
                } else {
                    int b = gm >> 11, s = gm & 2047;
                    int h = gn >> 7, hd = gn & 127;
                    *(float2*)&C[(((size_t)(b * H_NUM + h) * S_LEN) + s) * HD + hd] = v;
                }
            }
        }
    }
}

// ---------------------------------------------------------------------------
// fp32 -> (hi, lo) bf16 split, 4 elems/thread
// ---------------------------------------------------------------------------
__global__ void split_kernel(const float* __restrict__ X,
                             __nv_bfloat16* __restrict__ Hh,
                             __nv_bfloat16* __restrict__ Ll)
{
    size_t i = ((size_t)blockIdx.x * blockDim.x + threadIdx.x) * 4;
    float4 v = *(const float4*)(X + i);
    __nv_bfloat16 h0 = __float2bfloat16(v.x);
    __nv_bfloat16 h1 = __float2bfloat16(v.y);
    __nv_bfloat16 h2 = __float2bfloat16(v.z);
    __nv_bfloat16 h3 = __float2bfloat16(v.w);
    __nv_bfloat16 l0 = __float2bfloat16(v.x - __bfloat162float(h0));
    __nv_bfloat16 l1 = __float2bfloat16(v.y - __bfloat162float(h1));
    __nv_bfloat16 l2 = __float2bfloat16(v.z - __bfloat162float(h2));
    __nv_bfloat16 l3 = __float2bfloat16(v.w - __bfloat162float(h3));
    __nv_bfloat162* hp = (__nv_bfloat162*)(Hh + i);
    __nv_bfloat162* lp = (__nv_bfloat162*)(Ll + i);
    hp[0] = __nv_bfloat162(h0, h1); hp[1] = __nv_bfloat162(h2, h3);
    lp[0] = __nv_bfloat162(l0, l1); lp[1] = __nv_bfloat162(l2, l3);
}

// ---------------------------------------------------------------------------
// Weight transpose + split (unchanged)
// ---------------------------------------------------------------------------
__global__ void wtrans_kernel(const float* __restrict__ W0, const float* __restrict__ W1,
                              const float* __restrict__ W2, const float* __restrict__ W3,
                              __nv_bfloat16* __restrict__ TH,
                              __nv_bfloat16* __restrict__ TL)
{
    __shared__ float t[32][33];
    int z = blockIdx.z;
    const float* W = (z == 0) ? W0 : (z == 1 ? W1 : (z == 2 ? W2 : W3));
    __nv_bfloat16* th = TH + (size_t)z * D_DIM * KDIM;
    __nv_bfloat16* tl = TL + (size_t)z * D_DIM * KDIM;
    int k0 = blockIdx.y * 32, n0 = blockIdx.x * 32;
    int tx = threadIdx.x, ty = threadIdx.y;
#pragma unroll
    for (int i = 0; i < 4; i++)
        t[ty + 8 * i][tx] = W[(size_t)(k0 + ty + 8 * i) * D_DIM + n0 + tx];
    __syncthreads();
#pragma unroll
    for (int i = 0; i < 4; i++) {
        float v = t[tx][ty + 8 * i];
        __nv_bfloat16 h = __float2bfloat16(v);
        __nv_bfloat16 l = __float2bfloat16(v - __bfloat162float(h));
        size_t o = (size_t)(n0 + ty + 8 * i) * KDIM + k0 + tx;
        th[o] = h;
        tl[o] = l;
    }
}

// ---------------------------------------------------------------------------
// RoPE (exact Round-2 math) + bf16 hi/lo conversion.
// blockIdx.y: 0 = Q (rope + 1/sqrt(HD) scale), 1 = K (rope), 2 = V (convert).
// ---------------------------------------------------------------------------
__global__ void ropecvt_kernel(const float* __restrict__ Qf,
                               const float* __restrict__ Kf,
                               const float* __restrict__ Vf,
                               __nv_bfloat16* __restrict__ QH, __nv_bfloat16* __restrict__ QL,
                               __nv_bfloat16* __restrict__ KH, __nv_bfloat16* __restrict__ KL,
                               __nv_bfloat16* __restrict__ VH, __nv_bfloat16* __restrict__ VL)
{
    int which = blockIdx.y;
    const float* X = (which == 0) ? Qf : (which == 1 ? Kf : Vf);
    __nv_bfloat16* H = (which == 0) ? QH : (which == 1 ? KH : VH);
    __nv_bfloat16* L = (which == 0) ? QL : (which == 1 ? KL : VL);

    int flat = blockIdx.x * blockDim.x + threadIdx.x;  // < BH*S*64
    int i  = flat & 63;
    int s  = (flat >> 6) & 2047;
    int bh = flat >> 17;
    size_t base = ((size_t)bh * S_LEN + s) * HD + 2 * i;
    float x0 = X[base], x1 = X[base + 1];
    float y0, y1;
    if (which < 2) {
        int j0 = 2 * i, j1 = 2 * i + 1;
        const float nlog = -9.210340372f;  // -ln(10000)
        float f0 = __expf(nlog * (float)(j0 & 63) * (1.0f / 64.0f));
        float f1 = __expf(nlog * (float)(j1 & 63) * (1.0f / 64.0f));
        float a0 = (float)s * f0;
        float a1 = (float)s * f1;
        float c0, s0, c1, s1;
        sincosf(a0, &s0, &c0);
        sincosf(a1, &s1, &c1);
        y0 = x0 * c0 - x1 * s0;
        y1 = x1 * c1 + x0 * s1;
        if (which == 0) {
            const float scale = 0.08838834764831845f;  // 1/sqrt(128)
            y0 *= scale; y1 *= scale;
        }
    } else {
        y0 = x0; y1 = x1;
    }
    __nv_bfloat16 h0 = __float2bfloat16(y0);
    __nv_bfloat16 h1 = __float2bfloat16(y1);
    __nv_bfloat16 l0 = __float2bfloat16(y0 - __bfloat162float(h0));
    __nv_bfloat16 l1 = __float2bfloat16(y1 - __bfloat162float(h1));
    *(__nv_bfloat162*)(H + base) = __nv_bfloat162(h0, h1);
    *(__nv_bfloat162*)(L + base) = __nv_bfloat162(l0, l1);
}

// ---------------------------------------------------------------------------
// Tensor-core flash attention (bf16 split, fp32 softmax), causal.
// CTA = 128 q-rows of one bh. 8 warps x 16 rows. kv tiles of 64, double-buffered.
// ---------------------------------------------------------------------------
#define FR_STRIDE 272                       // 128 bf16 cols + 16B pad
#define FQ_BYTES  (128 * FR_STRIDE)         // 34816
#define FKV_MAT   (64 * FR_STRIDE)          // 17408
#define FSTAGE    (4 * FKV_MAT)             // Kh,Kl,Vh,Vl = 69632
#define FA2_SMEM  (2 * FQ_BYTES + 2 * FSTAGE)  // 208896

__device__ __forceinline__ void fa_load_kv(
    uint32_t st, const __nv_bfloat16* KH, const __nv_bfloat16* KL,
    const __nv_bfloat16* VH, const __nv_bfloat16* VL,
    int bh, int kb, int tid)
{
#pragma unroll
    for (int i = 0; i < 4; i++) {
        int idx = tid + i * 256;          // 0..1023
        int r = idx >> 4, ch = idx & 15;
        uint32_t off = (uint32_t)r * FR_STRIDE + ch * 16;
        size_t g = ((size_t)bh * S_LEN + kb * 64 + r) * HD + ch * 8;
        cp16(st + off,               KH + g);
        cp16(st + FKV_MAT + off,     KL + g);
        cp16(st + 2 * FKV_MAT + off, VH + g);
        cp16(st + 3 * FKV_MAT + off, VL + g);
    }
}

__global__ __launch_bounds__(256, 1)
void flash_mma_kernel(const __nv_bfloat16* __restrict__ QH,
                      const __nv_bfloat16* __restrict__ QL,
                      const __nv_bfloat16* __restrict__ KH,
                      const __nv_bfloat16* __restrict__ KL,
                      const __nv_bfloat16* __restrict__ VH,
                      const __nv_bfloat16* __restrict__ VL,
                      float* __restrict__ Out)
{
    extern __shared__ __align__(256) char smem[];
    uint32_t sb = smem_u32(smem);
    const uint32_t uQH = sb, uQL = sb + FQ_BYTES;
    const uint32_t uST0 = sb + 2 * FQ_BYTES;

    int tid = threadIdx.x;
    int wid = tid >> 5, lane = tid & 31;
    int qb = 15 - blockIdx.x;        // big blocks first
    int bh = blockIdx.y;
    int nkb = 2 * qb + 2;

    // ---- prologue loads: Q (group 0), KV0 (group 1), KV1 (group 2) ----
#pragma unroll
    for (int i = 0; i < 8; i++) {
        int idx = tid + i * 256;      // 0..2047
        int r = idx >> 4, ch = idx & 15;
        uint32_t off = (uint32_t)r * FR_STRIDE + ch * 16;
        size_t g = ((size_t)bh * S_LEN + qb * 128 + r) * HD + ch * 8;
        cp16(uQH + off, QH + g);
        cp16(uQL + off, QL + g);
    }
    CP_COMMIT();
    fa_load_kv(uST0, KH, KL, VH, VL, bh, 0, tid); CP_COMMIT();
    if (nkb > 1) { fa_load_kv(uST0 + FSTAGE, KH, KL, VH, VL, bh, 1, tid); CP_COMMIT(); }

    float accO[16][4];
#pragma unroll
    for (int j = 0; j < 16; j++)
#pragma unroll
        for (int t = 0; t < 4; t++) accO[j][t] = 0.f;
    float m0v = -INFINITY, m1v = -INFINITY, l0v = 0.f, l1v = 0.f;

    // ldmatrix lane addressing (constants per thread)
    uint32_t q_ao = (uint32_t)(wid * 16 + (lane & 15)) * FR_STRIDE + ((lane >> 4) & 1) * 16;
    uint32_t k_bo = (uint32_t)((lane & 7) + (((lane >> 4) & 1) << 3)) * FR_STRIDE
                    + ((lane >> 3) & 1) * 16;
    uint32_t v_to = (uint32_t)(lane & 15) * FR_STRIDE + ((lane >> 4) & 1) * 16;

    if (nkb > 1) { CP_WAIT1(); } else { CP_WAIT0(); }
    __syncthreads();

    for (int kb = 0; kb < nkb; kb++) {
        uint32_t st = uST0 + (uint32_t)(kb & 1) * FSTAGE;
        uint32_t stKH = st, stKL = st + FKV_MAT;
        uint32_t stVH = st + 2 * FKV_MAT, stVL = st + 3 * FKV_MAT;

        // ---- S = Q K^T (3-term) ----
        float accS[8][4];
#pragma unroll
        for (int j = 0; j < 8; j++)
#pragma unroll
            for (int t = 0; t < 4; t++) accS[j][t] = 0.f;

#pragma unroll
        for (int ks = 0; ks < 8; ks++) {
            uint32_t qh[4], ql[4];
            ldsm4(qh, uQH + q_ao + ks * 32);
            ldsm4(ql, uQL + q_ao + ks * 32);
#pragma unroll
            for (int j = 0; j < 4; j++) {
                uint32_t kh[4], kl[4];
                uint32_t bo = k_bo + (uint32_t)j * 16 * FR_STRIDE + ks * 32;
                ldsm4(kh, stKH + bo);
                ldsm4(kl, stKL + bo);
                mma_bf16(accS[2 * j],     qh, &kh[0]);
                mma_bf16(accS[2 * j + 1], qh, &kh[2]);
                mma_bf16(accS[2 * j],     qh, &kl[0]);
                mma_bf16(accS[2 * j + 1], qh, &kl[2]);
                mma_bf16(accS[2 * j],     ql, &kh[0]);
                mma_bf16(accS[2 * j + 1], ql, &kh[2]);
            }
        }

        // ---- causal mask (only near diagonal) ----
        if (kb >= 2 * qb) {
            int grow = qb * 128 + wid * 16 + (lane >> 2);
#pragma unroll
            for (int j = 0; j < 8; j++) {
                int col = kb * 64 + j * 8 + ((lane & 3) << 1);
                if (col     > grow)     accS[j][0] = -INFINITY;
                if (col + 1 > grow)     accS[j][1] = -INFINITY;
                if (col     > grow + 8) accS[j][2] = -INFINITY;
                if (col + 1 > grow + 8) accS[j][3] = -INFINITY;
            }
        }

        // ---- online softmax (rows r0 = lane>>2, r1 = r0+8; quad-local) ----
        float rm0 = -INFINITY, rm1 = -INFINITY;
#pragma unroll
        for (int j = 0; j < 8; j++) {
            rm0 = fmaxf(rm0, fmaxf(accS[j][0], accS[j][1]));
            rm1 = fmaxf(rm1, fmaxf(accS[j][2], accS[j][3]));
        }
        rm0 = fmaxf(rm0, __shfl_xor_sync(0xffffffffu, rm0, 1));
        rm0 = fmaxf(rm0, __shfl_xor_sync(0xffffffffu, rm0, 2));
        rm1 = fmaxf(rm1, __shfl_xor_sync(0xffffffffu, rm1, 1));
        rm1 = fmaxf(rm1, __shfl_xor_sync(0xffffffffu, rm1, 2));

        float mn0 = fmaxf(m0v, rm0), mn1 = fmaxf(m1v, rm1);
        float al0 = __expf(m0v - mn0), al1 = __expf(m1v - mn1);
        m0v = mn0; m1v = mn1;

        float rs0 = 0.f, rs1 = 0.f;
#pragma unroll
        for (int j = 0; j < 8; j++) {
            accS[j][0] = __expf(accS[j][0] - mn0);
            accS[j][1] = __expf(accS[j][1] - mn0);
            accS[j][2] = __expf(accS[j][2] - mn1);
            accS[j][3] = __expf(accS[j][3] - mn1);
            rs0 += accS[j][0] + accS[j][1];
            rs1 += accS[j][2] + accS[j][3];
        }
        rs0 += __shfl_xor_sync(0xffffffffu, rs0, 1);
        rs0 += __shfl_xor_sync(0xffffffffu, rs0, 2);
        rs1 += __shfl_xor_sync(0xffffffffu, rs1, 1);
        rs1 += __shfl_xor_sync(0xffffffffu, rs1, 2);
        l0v = l0v * al0 + rs0;
        l1v = l1v * al1 + rs1;

#pragma unroll
        for (int j = 0; j < 16; j++) {
            accO[j][0] *= al0; accO[j][1] *= al0;
            accO[j][2] *= al1; accO[j][3] *= al1;
        }

        // ---- P fragments in registers (C-frag == A-frag layout identity) ----
        uint32_t pa_h[8][2], pa_l[8][2];
#pragma unroll
        for (int j = 0; j < 8; j++) {
            __nv_bfloat16 h0 = __float2bfloat16(accS[j][0]);
            __nv_bfloat16 h1 = __float2bfloat16(accS[j][1]);
            __nv_bfloat16 h2 = __float2bfloat16(accS[j][2]);
            __nv_bfloat16 h3 = __float2bfloat16(accS[j][3]);
            __nv_bfloat16 e0 = __float2bfloat16(accS[j][0] - __bfloat162float(h0));
            __nv_bfloat16 e1 = __float2bfloat16(accS[j][1] - __bfloat162float(h1));
            __nv_bfloat16 e2 = __float2bfloat16(accS[j][2] - __bfloat162float(h2));
            __nv_bfloat16 e3 = __float2bfloat16(accS[j][3] - __bfloat162float(h3));
            pa_h[j][0] = ((uint32_t)__bfloat16_as_ushort(h1) << 16) | __bfloat16_as_ushort(h0);
            pa_h[j][1] = ((uint32_t)__bfloat16_as_ushort(h3) << 16) | __bfloat16_as_ushort(h2);
            pa_l[j][0] = ((uint32_t)__bfloat16_as_ushort(e1) << 16) | __bfloat16_as_ushort(e0);
            pa_l[j][1] = ((uint32_t)__bfloat16_as_ushort(e3) << 16) | __bfloat16_as_ushort(e2);
        }

        // ---- O += P V (3-term), V via ldmatrix.trans ----
#pragma unroll
        for (int ks = 0; ks < 4; ks++) {
            uint32_t ah4[4] = { pa_h[2 * ks][0], pa_h[2 * ks][1],
                                pa_h[2 * ks + 1][0], pa_h[2 * ks + 1][1] };
            uint32_t al4[4] = { pa_l[2 * ks][0], pa_l[2 * ks][1],
                                pa_l[2 * ks + 1][0], pa_l[2 * ks + 1][1] };
#pragma unroll
            for (int j2 = 0; j2 < 8; j2++) {
                uint32_t vh[4], vl[4];
                uint32_t vo = v_to + (uint32_t)ks * 16 * FR_STRIDE + j2 * 32;
                ldsm4t(vh, stVH + vo);
                ldsm4t(vl, stVL + vo);
                mma_bf16(accO[2 * j2],     ah4, &vh[0]);
                mma_bf16(accO[2 * j2 + 1], ah4, &vh[2]);
                mma_bf16(accO[2 * j2],     ah4, &vl[0]);
                mma_bf16(accO[2 * j2 + 1], ah4, &vl[2]);
                mma_bf16(accO[2 * j2],     al4, &vh[0]);
                mma_bf16(accO[2 * j2 + 1], al4, &vh[2]);
            }
        }

        __syncthreads();   // all warps done with this stage
        if (kb + 2 < nkb) {
            fa_load_kv(st, KH, KL, VH, VL, bh, kb + 2, tid);
            CP_COMMIT();
        }
        if (kb + 1 < nkb) {
            if (kb + 2 < nkb) { CP_WAIT1(); } else { CP_WAIT0(); }
            __syncthreads();
        }
    }

    // ---- epilogue: normalize, write [B][S][D] ----
    int b = bh >> 4, h = bh & 15;
    int srow = qb * 128 + wid * 16 + (lane >> 2);
    float inv0 = 1.0f / l0v, inv1 = 1.0f / l1v;
#pragma unroll
    for (int j = 0; j < 16; j++) {
        int col = h * HD + j * 8 + ((lane & 3) << 1);
        size_t o0 = ((size_t)b * S_LEN + srow) * D_DIM + col;
        size_t o1 = ((size_t)b * S_LEN + srow + 8) * D_DIM + col;
        *(float2*)&Out[o0] = make_float2(accO[j][0] * inv0, accO[j][1] * inv0);
        *(float2*)&Out[o1] = make_float2(accO[j][2] * inv1, accO[j][3] * inv1);
    }
}

// ---------------------------------------------------------------------------
extern "C" void kernel_launch(void* const* d_in, const int* in_sizes, int n_in,
                              void* d_out, int out_size)
{
    const float* x  = (const float*)d_in[0];
    const float* Wq = (const float*)d_in[1];
    const float* Wk = (const float*)d_in[2];
    const float* Wv = (const float*)d_in[3];
    const float* Wo = (const float*)d_in[4];
    float* out = (float*)d_out;

    float *pq, *pk, *pv, *pa;
    __nv_bfloat16 *pah, *pal, *pwh, *pwl;
    __nv_bfloat16 *pqh, *pql, *pkh, *pkl, *pvh, *pvl;
    cudaGetSymbolAddress((void**)&pq,  g_q);
    cudaGetSymbolAddress((void**)&pk,  g_k);
    cudaGetSymbolAddress((void**)&pv,  g_v);
    cudaGetSymbolAddress((void**)&pa,  g_att);
    cudaGetSymbolAddress((void**)&pah, g_ah);
    cudaGetSymbolAddress((void**)&pal, g_al);
    cudaGetSymbolAddress((void**)&pwh, g_wth);
    cudaGetSymbolAddress((void**)&pwl, g_wtl);
    cudaGetSymbolAddress((void**)&pqh, g_qh);
    cudaGetSymbolAddress((void**)&pql, g_ql);
    cudaGetSymbolAddress((void**)&pkh, g_kh);
    cudaGetSymbolAddress((void**)&pkl, g_kl);
    cudaGetSymbolAddress((void**)&pvh, g_vh);
    cudaGetSymbolAddress((void**)&pvl, g_vl);

    cudaFuncSetAttribute(mma_gemm_kernel,
                         cudaFuncAttributeMaxDynamicSharedMemorySize, MG_SMEM);
    cudaFuncSetAttribute(flash_mma_kernel,
                         cudaFuncAttributeMaxDynamicSharedMemorySize, FA2_SMEM);

    // 1) bf16 splits of x and the (transposed) weights
    split_kernel<<<(M_ROWS * KDIM / 4) / 256, 256>>>(x, pah, pal);
    wtrans_kernel<<<dim3(D_DIM / 32, KDIM / 32, 4), dim3(32, 8)>>>(
        Wq, Wk, Wv, Wo, pwh, pwl);

    // 2) QKV projections (tensor cores), write [B,H,S,HD] fp32
    mma_gemm_kernel<<<dim3(D_DIM / 128, M_ROWS / 128, 3), 256, MG_SMEM>>>(
        pah, pal, pwh, pwl, pq, pk, pv, 0, 1);

    // 3) RoPE + bf16 hi/lo conversion of Q (scaled), K, V
    ropecvt_kernel<<<dim3(4194304 / 256, 3), 256>>>(
        pq, pk, pv, pqh, pql, pkh, pkl, pvh, pvl);

    // 4) tensor-core causal flash attention -> g_att [B,S,D]
    flash_mma_kernel<<<dim3(S_LEN / 128, BH_NUM), 256, FA2_SMEM>>>(
        pqh, pql, pkh, pkl, pvh, pvl, pa);

    // 5) split attention output, then O projection -> d_out
    split_kernel<<<(M_ROWS * KDIM / 4) / 256, 256>>>(pa, pah, pal);
    mma_gemm_kernel<<<dim3(D_DIM / 128, M_ROWS / 128, 1), 256, MG_SMEM>>>(
        pah, pal, pwh, pwl, out, out, out, 3, 0);
}